// round 1
// baseline (speedup 1.0000x reference)
#include <cuda_runtime.h>

// Problem constants
#define B_SZ    1024
#define K_SEQ   16
#define D_DIM   1024
#define H_NUM   16
#define HD      64
#define NIRR    16

#define GM      (B_SZ * K_SEQ)   // 16384
#define GN      D_DIM            // 1024
#define GK      D_DIM            // 1024

// ---------------- scratch (device globals: no allocations allowed) ----------
__device__ float g_Q[GM * GN];
__device__ float g_K[GM * GN];
__device__ float g_V[GM * GN];
__device__ float g_T[GM * GN];

// ---------------- SGEMM: C = A[GM,GK] * B[GK,GN] + bias (row broadcast) -----
#define BM 128
#define BN 128
#define BK 8

__global__ __launch_bounds__(256) void sgemm_bias(
    const float* __restrict__ A, const float* __restrict__ Bm,
    const float* __restrict__ bias, float* __restrict__ C)
{
    __shared__ float As[BK][BM];
    __shared__ float Bs[BK][BN];

    const int tid  = threadIdx.x;
    const int brow = blockIdx.y * BM;
    const int bcol = blockIdx.x * BN;

    // A tile load mapping: 128 rows x 8 k-cols, one float4 per thread
    const int ar = tid >> 1;           // 0..127
    const int ac = (tid & 1) << 2;     // 0 or 4
    // B tile load mapping: 8 k-rows x 128 n-cols, one float4 per thread
    const int br = tid >> 5;           // 0..7
    const int bc = (tid & 31) << 2;    // 0..124

    const int ty = tid >> 4;           // 0..15  (row group)
    const int tx = tid & 15;           // 0..15  (col group)

    const float* Ap = A  + (size_t)(brow + ar) * GK + ac;
    const float* Bp = Bm + (size_t)br * GN + bcol + bc;

    float acc[8][8];
#pragma unroll
    for (int i = 0; i < 8; i++)
#pragma unroll
        for (int j = 0; j < 8; j++) acc[i][j] = 0.f;

    for (int k0 = 0; k0 < GK; k0 += BK) {
        float4 av = *(const float4*)(Ap + k0);
        As[ac + 0][ar] = av.x;
        As[ac + 1][ar] = av.y;
        As[ac + 2][ar] = av.z;
        As[ac + 3][ar] = av.w;
        *(float4*)&Bs[br][bc] = *(const float4*)(Bp + (size_t)k0 * GN);
        __syncthreads();

#pragma unroll
        for (int kk = 0; kk < BK; kk++) {
            float af[8], bf[8];
#pragma unroll
            for (int u = 0; u < 8; u++) af[u] = As[kk][ty * 8 + u];
#pragma unroll
            for (int u = 0; u < 8; u++) bf[u] = Bs[kk][tx * 8 + u];
#pragma unroll
            for (int iy = 0; iy < 8; iy++)
#pragma unroll
                for (int ix = 0; ix < 8; ix++)
                    acc[iy][ix] += af[iy] * bf[ix];
        }
        __syncthreads();
    }

#pragma unroll
    for (int iy = 0; iy < 8; iy++) {
        float* Crow = C + (size_t)(brow + ty * 8 + iy) * GN + bcol + tx * 8;
        const float* brow_b = bias + bcol + tx * 8;
#pragma unroll
        for (int ix = 0; ix < 8; ix += 4) {
            float4 o;
            o.x = acc[iy][ix + 0] + brow_b[ix + 0];
            o.y = acc[iy][ix + 1] + brow_b[ix + 1];
            o.z = acc[iy][ix + 2] + brow_b[ix + 2];
            o.w = acc[iy][ix + 3] + brow_b[ix + 3];
            *(float4*)(Crow + ix) = o;
        }
    }
}

// ---------------- per-(b,h) irrep attention ---------------------------------
// out = [ sum_p softmax(scale * P S P^T) P ] V,  with S = Q K^T (16x16)
__global__ __launch_bounds__(256) void psead_attn(
    const float* __restrict__ Qg, const float* __restrict__ Kg,
    const float* __restrict__ Vg, const float* __restrict__ proj,
    float* __restrict__ Tg)
{
    __shared__ float sq[16][65];
    __shared__ float sk[16][65];
    __shared__ float sv[16][65];
    __shared__ float sP[NIRR][16][16];
    __shared__ float sS[16][17];
    __shared__ float sT[16][17];
    __shared__ float sW[16][17];
    __shared__ float sM[16][17];

    const int tid = threadIdx.x;
    const int b   = blockIdx.x >> 4;
    const int h   = blockIdx.x & 15;
    const size_t base = (size_t)b * (K_SEQ * D_DIM) + (size_t)h * HD;

    // load Q/K/V head tiles [16 x 64], one float4 per thread per matrix
    {
        const int r  = tid >> 4;
        const int c4 = (tid & 15) << 2;
        float4 qv = *(const float4*)(Qg + base + (size_t)r * D_DIM + c4);
        sq[r][c4 + 0] = qv.x; sq[r][c4 + 1] = qv.y; sq[r][c4 + 2] = qv.z; sq[r][c4 + 3] = qv.w;
        float4 kv = *(const float4*)(Kg + base + (size_t)r * D_DIM + c4);
        sk[r][c4 + 0] = kv.x; sk[r][c4 + 1] = kv.y; sk[r][c4 + 2] = kv.z; sk[r][c4 + 3] = kv.w;
        float4 vv = *(const float4*)(Vg + base + (size_t)r * D_DIM + c4);
        sv[r][c4 + 0] = vv.x; sv[r][c4 + 1] = vv.y; sv[r][c4 + 2] = vv.z; sv[r][c4 + 3] = vv.w;
    }
    // load all 16 projectors (contiguous 4096 floats)
    {
        const float4* p4 = (const float4*)proj;
        float4* dst = (float4*)&sP[0][0][0];
#pragma unroll
        for (int t = 0; t < 4; t++) dst[tid + t * 256] = p4[tid + t * 256];
    }
    __syncthreads();

    const int i = tid >> 4;   // row 0..15
    const int j = tid & 15;   // col 0..15

    // S = scale * Q K^T
    {
        float s = 0.f;
#pragma unroll
        for (int d = 0; d < HD; d++) s += sq[i][d] * sk[j][d];
        sS[i][j] = s * 0.125f;   // 1/sqrt(64)
    }
    __syncthreads();

    float m_acc = 0.f;
    for (int p = 0; p < NIRR; p++) {
        // T = P * S
        float t = 0.f;
#pragma unroll
        for (int u = 0; u < 16; u++) t += sP[p][i][u] * sS[u][j];
        sT[i][j] = t;
        __syncthreads();

        // s2 = (P S) P^T :  s2[i][j] = sum_v T[i][v] * P[j][v]
        float s2 = 0.f;
#pragma unroll
        for (int v = 0; v < 16; v++) s2 += sT[i][v] * sP[p][j][v];

        // softmax over j within row i (rows live in 16-lane half-warps)
        float mx = s2;
#pragma unroll
        for (int o = 8; o > 0; o >>= 1)
            mx = fmaxf(mx, __shfl_xor_sync(0xffffffffu, mx, o));
        float e = __expf(s2 - mx);
        float se = e;
#pragma unroll
        for (int o = 8; o > 0; o >>= 1)
            se += __shfl_xor_sync(0xffffffffu, se, o);
        sW[i][j] = e / se;
        __syncthreads();

        // M += W * P : sum_v W[i][v] * P[v][j]
        float mm = 0.f;
#pragma unroll
        for (int v = 0; v < 16; v++) mm += sW[i][v] * sP[p][v][j];
        m_acc += mm;
        // no barrier needed here: next iteration's sT write is fenced by its
        // own __syncthreads before any thread reads it, and sW of iter p+1 is
        // written only after the post-sT barrier of p+1.
        __syncthreads();
    }

    sM[i][j] = m_acc;
    __syncthreads();

    // out[i][d] = sum_v M[i][v] * V[v][d]; thread handles 4 consecutive d
    {
        const int d0 = j << 2;
        float o0 = 0.f, o1 = 0.f, o2 = 0.f, o3 = 0.f;
#pragma unroll
        for (int v = 0; v < 16; v++) {
            const float mv = sM[i][v];
            o0 += mv * sv[v][d0 + 0];
            o1 += mv * sv[v][d0 + 1];
            o2 += mv * sv[v][d0 + 2];
            o3 += mv * sv[v][d0 + 3];
        }
        float4 ov = make_float4(o0, o1, o2, o3);
        *(float4*)(Tg + base + (size_t)i * D_DIM + d0) = ov;
    }
}

// ---------------- launch -----------------------------------------------------
extern "C" void kernel_launch(void* const* d_in, const int* in_sizes, int n_in,
                              void* d_out, int out_size)
{
    (void)in_sizes; (void)n_in; (void)out_size;
    const float* x    = (const float*)d_in[0];
    const float* proj = (const float*)d_in[1];
    const float* Wq   = (const float*)d_in[2];
    const float* bq   = (const float*)d_in[3];
    const float* Wk   = (const float*)d_in[4];
    const float* bk   = (const float*)d_in[5];
    const float* Wv   = (const float*)d_in[6];
    const float* bv   = (const float*)d_in[7];
    const float* Wo   = (const float*)d_in[8];
    const float* bo   = (const float*)d_in[9];
    float* out = (float*)d_out;

    float *Qb, *Kb, *Vb, *Tb;
    cudaGetSymbolAddress((void**)&Qb, g_Q);
    cudaGetSymbolAddress((void**)&Kb, g_K);
    cudaGetSymbolAddress((void**)&Vb, g_V);
    cudaGetSymbolAddress((void**)&Tb, g_T);

    dim3 gg(GN / BN, GM / BM);   // (8, 128)
    sgemm_bias<<<gg, 256>>>(x, Wq, bq, Qb);
    sgemm_bias<<<gg, 256>>>(x, Wk, bk, Kb);
    sgemm_bias<<<gg, 256>>>(x, Wv, bv, Vb);

    psead_attn<<<B_SZ * H_NUM, 256>>>(Qb, Kb, Vb, proj, Tb);

    sgemm_bias<<<gg, 256>>>(Tb, Wo, bo, out);
}